// round 4
// baseline (speedup 1.0000x reference)
#include <cuda_runtime.h>

// Problem dims
#define N_   128
#define C_   64
#define T_   288
#define V_   16
#define S_   3
#define IC_  16
#define KCT  (IC_*T_)      // 4608
#define TV_  (T_*V_)       // 4608

// Kernel 1 tiling
#define TT1  8
#define J1   (TT1*V_)      // 128
#define NCH  (T_/TT1)      // 36

// Kernel 3 tiling
#define TT3  8
#define J3   (TT3*V_)      // 128
#define NCH3 (T_/TT3)      // 36
#define RS3  130           // xs/zs row stride: even, bank stride 2 for column access

// Scratch (no cudaMalloc allowed)
__device__ float g_partial[(long)N_*NCH*S_*V_*V_];   // [n][ch][s][v*16+w]
__device__ float g_att[(long)N_*S_*V_*V_];           // [n][s][v*16+w]
__device__ float g_WaT[S_*C_*IC_];                   // [s][c][i]
__device__ float g_WbT[S_*C_*IC_];
__device__ float g_WdT[S_*C_*C_];                    // [s][c][o]

typedef unsigned long long u64;

__device__ __forceinline__ u64 splat2(float x) {
    u64 r; asm("mov.b64 %0, {%1, %1};" : "=l"(r) : "f"(x)); return r;
}
__device__ __forceinline__ void fma2(u64& d, u64 a, u64 b) {
    asm("fma.rn.f32x2 %0, %1, %2, %0;" : "+l"(d) : "l"(a), "l"(b));
}
__device__ __forceinline__ u64 add2(u64 a, u64 b) {
    u64 r; asm("add.rn.f32x2 %0, %1, %2;" : "=l"(r) : "l"(a), "l"(b)); return r;
}
__device__ __forceinline__ float2 unpack2(u64 a) {
    float2 r; asm("mov.b64 {%0, %1}, %2;" : "=f"(r.x), "=f"(r.y) : "l"(a)); return r;
}

// ---------------------------------------------------------------------------
// Kernel 0: pre-transpose weights (tiny, one block).
// ---------------------------------------------------------------------------
extern "C" __global__ void k0_transpose(const float* __restrict__ Wa,
                                        const float* __restrict__ Wb,
                                        const float* __restrict__ Wd)
{
    const int tid = threadIdx.x;
    for (int idx = tid; idx < S_*C_*IC_; idx += 256) {
        int i = idx & 15, c = (idx >> 4) & 63, s = idx >> 10;
        g_WaT[idx] = Wa[(s*16 + i)*64 + c];
        g_WbT[idx] = Wb[(s*16 + i)*64 + c];
    }
    for (int idx = tid; idx < S_*C_*C_; idx += 256) {
        int o = idx & 63, c = (idx >> 6) & 63, s = idx >> 12;
        g_WdT[idx] = Wd[(s*64 + o)*64 + c];
    }
}

// ---------------------------------------------------------------------------
// Kernel 1: att logit partials. Grid (NCH, N), 256 threads, occ 4.
// Weights read from global via warp-uniform broadcast LDG (L1-resident).
// ---------------------------------------------------------------------------
#define SM1_XS   0
#define SM1_FA   8192
#define SM1_FB   10240
#define SM1_ATTP 12288
#define SMEM1_BYTES ((12288 + 1024)*4)   // 53248 B

extern "C" __global__ void __launch_bounds__(256, 4)
k1_att_partial(const float* __restrict__ x,
               const float* __restrict__ ba, const float* __restrict__ bb)
{
    extern __shared__ float sm[];
    float* xs   = sm + SM1_XS;    // [64][128]
    float* fas  = sm + SM1_FA;    // [16][128]
    float* fbs  = sm + SM1_FB;    // [16][128]
    float* attp = sm + SM1_ATTP;  // [4][256]

    const int ch  = blockIdx.x;
    const int n   = blockIdx.y;
    const int tid = threadIdx.x;
    const int lane = tid & 31, wrp = tid >> 5;

    const long xbase = (long)n*C_*TV_ + (long)(ch*TT1)*V_;
    for (int idx = tid; idx < 4096; idx += 256) {
        int c = idx >> 6, jp = (idx & 63)*2;
        *(u64*)&xs[c*128 + jp] = *(const u64*)&x[xbase + (long)c*TV_ + jp];
    }
    __syncthreads();

    // phase1 mapping: 4 i x one u64 j
    const int i0   = (wrp & 3)*4;
    const int jcol = 64*(wrp >> 2) + 2*lane;
    // phase2 mapping
    const int q  = tid >> 6;
    const int pv = (tid >> 3) & 7;
    const int pw = tid & 7;

    for (int s = 0; s < S_; s++) {
        // ---- phase 1: fa/fb tiles ----
        u64 aA[4], aB[4];
        #pragma unroll
        for (int ii = 0; ii < 4; ii++) { aA[ii] = 0ull; aB[ii] = 0ull; }
        const float* wap = &g_WaT[s*1024 + i0];
        const float* wbp = &g_WbT[s*1024 + i0];
        #pragma unroll 4
        for (int c = 0; c < 64; c++) {
            u64 xq = *(const u64*)&xs[c*128 + jcol];   // 2 phases
            float4 wa4 = __ldg((const float4*)&wap[c*16]);  // uniform bcast
            float4 wb4 = __ldg((const float4*)&wbp[c*16]);
            fma2(aA[0], splat2(wa4.x), xq);
            fma2(aA[1], splat2(wa4.y), xq);
            fma2(aA[2], splat2(wa4.z), xq);
            fma2(aA[3], splat2(wa4.w), xq);
            fma2(aB[0], splat2(wb4.x), xq);
            fma2(aB[1], splat2(wb4.y), xq);
            fma2(aB[2], splat2(wb4.z), xq);
            fma2(aB[3], splat2(wb4.w), xq);
        }
        #pragma unroll
        for (int ii = 0; ii < 4; ii++) {
            u64 fav = add2(aA[ii], splat2(ba[s*16 + i0 + ii]));
            u64 fbv = add2(aB[ii], splat2(bb[s*16 + i0 + ii]));
            *(u64*)&fas[(i0 + ii)*128 + jcol] = fav;
            *(u64*)&fbs[(i0 + ii)*128 + jcol] = fbv;
        }
        __syncthreads();

        // ---- phase 2: 2v x 2w tile, term-split 4 ways ----
        u64 acc0 = 0ull, acc1 = 0ull;
        #pragma unroll 8
        for (int r = 0; r < 32; r++) {
            int term = q*32 + r;
            u64 fp = *(const u64*)&fas[term*16 + 2*pv];
            u64 gp = *(const u64*)&fbs[term*16 + 2*pw];
            float2 f2 = unpack2(fp);
            fma2(acc0, splat2(f2.x), gp);
            fma2(acc1, splat2(f2.y), gp);
        }
        *(u64*)&attp[q*256 + (2*pv  )*16 + 2*pw] = acc0;
        *(u64*)&attp[q*256 + (2*pv+1)*16 + 2*pw] = acc1;
        __syncthreads();

        float red = attp[tid] + attp[256 + tid] + attp[512 + tid] + attp[768 + tid];
        g_partial[(((long)n*NCH + ch)*S_ + s)*256 + tid] = red;
    }
}

// ---------------------------------------------------------------------------
// Kernel 2: reduce chunks, /K, softmax over v, + (A_base + PA).
// ---------------------------------------------------------------------------
extern "C" __global__ void k2_softmax(const float* __restrict__ Abase,
                                      const float* __restrict__ PA)
{
    const int b = blockIdx.x;          // n*3 + s
    const int n = b / S_, s = b % S_;
    const int tid = threadIdx.x;       // v*16 + w
    const int w = tid & 15;

    __shared__ float sv[256];
    __shared__ float se[256];

    float sum = 0.f;
    const float* p = &g_partial[((long)n*NCH)*S_*256 + s*256 + tid];
    for (int chv = 0; chv < NCH; chv++) sum += p[(long)chv * (S_*256)];
    float val = sum * (1.0f / (float)KCT);

    sv[tid] = val;
    __syncthreads();
    float m = -1e30f;
    #pragma unroll
    for (int vv = 0; vv < 16; vv++) m = fmaxf(m, sv[vv*16 + w]);
    float e = expf(val - m);
    se[tid] = e;
    __syncthreads();
    float ss = 0.f;
    #pragma unroll
    for (int vv = 0; vv < 16; vv++) ss += se[vv*16 + w];

    float a = e / ss + Abase[s*256 + tid] + PA[s*256 + tid];
    g_att[(long)b*256 + tid] = a;
}

// ---------------------------------------------------------------------------
// Kernel 3: z = x @ att (smem), y = sum_s Wd_s @ z_s, BN+bias+residual.
// Grid (NCH3, N), 256 threads, occ 2 via slim smem (Wd stays in global,
// warp-uniform broadcast, L1-resident).
// ---------------------------------------------------------------------------
#define SM3_XS   0
#define SM3_ZS   (64*RS3)            // 8320
#define SM3_ATT  (2*64*RS3)          // 16640
#define SMEM3_BYTES ((2*64*RS3 + S_*256)*4)   // 69632 B

extern "C" __global__ void __launch_bounds__(256, 2)
k3_out(const float* __restrict__ x,
       const float* __restrict__ bd, const float* __restrict__ gamma,
       const float* __restrict__ beta, float* __restrict__ out)
{
    extern __shared__ float sm[];
    float* xs   = sm + SM3_XS;    // [64][RS3]
    float* zs   = sm + SM3_ZS;    // [64][RS3]
    float* atts = sm + SM3_ATT;   // [s][v][w]

    const int ch  = blockIdx.x;
    const int n   = blockIdx.y;
    const int tid = threadIdx.x;
    const int lane = tid & 31, wrp = tid >> 5;

    const long xbase = (long)n*C_*TV_ + (long)(ch*TT3)*V_;
    for (int idx = tid; idx < 64*64; idx += 256) {
        int c = idx >> 6, jp = (idx & 63)*2;
        *(u64*)&xs[c*RS3 + jp] = *(const u64*)&x[xbase + (long)c*TV_ + jp];
    }
    for (int idx = tid; idx < S_*256; idx += 256)
        atts[idx] = g_att[(long)n*S_*256 + idx];
    __syncthreads();

    // z mapping: thread owns rows {lane, lane+32} at t' = wrp (8 warps)
    const int ca = lane, cb = lane + 32;
    const int jz = wrp * 16;
    // y mapping: 8 o per warp x 2 u64 j per thread
    const int o0 = wrp * 8;
    const int jA = 2*lane, jB = 2*lane + 64;

    u64 yacc[16];
    #pragma unroll
    for (int k = 0; k < 16; k++) yacc[k] = 0ull;

    for (int s = 0; s < S_; s++) {
        // ---- z tile ----
        u64 zacc[16];
        #pragma unroll
        for (int k = 0; k < 16; k++) zacc[k] = 0ull;
        const float* ap = &atts[s*256];
        #pragma unroll
        for (int v = 0; v < 16; v++) {
            ulonglong2 arq0 = *(const ulonglong2*)&ap[v*16 +  0];  // bcast
            ulonglong2 arq1 = *(const ulonglong2*)&ap[v*16 +  4];
            ulonglong2 arq2 = *(const ulonglong2*)&ap[v*16 +  8];
            ulonglong2 arq3 = *(const ulonglong2*)&ap[v*16 + 12];
            u64 xa = splat2(xs[ca*RS3 + jz + v]);   // 2-way max
            u64 xb = splat2(xs[cb*RS3 + jz + v]);
            fma2(zacc[0], xa, arq0.x); fma2(zacc[1], xa, arq0.y);
            fma2(zacc[2], xa, arq1.x); fma2(zacc[3], xa, arq1.y);
            fma2(zacc[4], xa, arq2.x); fma2(zacc[5], xa, arq2.y);
            fma2(zacc[6], xa, arq3.x); fma2(zacc[7], xa, arq3.y);
            fma2(zacc[ 8], xb, arq0.x); fma2(zacc[ 9], xb, arq0.y);
            fma2(zacc[10], xb, arq1.x); fma2(zacc[11], xb, arq1.y);
            fma2(zacc[12], xb, arq2.x); fma2(zacc[13], xb, arq2.y);
            fma2(zacc[14], xb, arq3.x); fma2(zacc[15], xb, arq3.y);
        }
        #pragma unroll
        for (int p = 0; p < 8; p++) {
            *(u64*)&zs[ca*RS3 + jz + 2*p] = zacc[p];
            *(u64*)&zs[cb*RS3 + jz + 2*p] = zacc[8 + p];
        }
        __syncthreads();

        // ---- y += Wd_s @ z_s (Wd from global, warp-uniform) ----
        const float* wp = &g_WdT[s*4096 + o0];
        #pragma unroll 4
        for (int c = 0; c < 64; c++) {
            float4 wA = __ldg((const float4*)&wp[c*64]);      // bcast
            float4 wB = __ldg((const float4*)&wp[c*64 + 4]);  // bcast
            const float* zr = &zs[c*RS3];
            u64 z0 = *(const u64*)&zr[jA];                    // lane-consec
            u64 z1 = *(const u64*)&zr[jB];
            u64 w0 = splat2(wA.x), w1 = splat2(wA.y), w2 = splat2(wA.z), w3 = splat2(wA.w);
            u64 w4 = splat2(wB.x), w5 = splat2(wB.y), w6 = splat2(wB.z), w7 = splat2(wB.w);
            fma2(yacc[ 0], w0, z0); fma2(yacc[ 1], w0, z1);
            fma2(yacc[ 2], w1, z0); fma2(yacc[ 3], w1, z1);
            fma2(yacc[ 4], w2, z0); fma2(yacc[ 5], w2, z1);
            fma2(yacc[ 6], w3, z0); fma2(yacc[ 7], w3, z1);
            fma2(yacc[ 8], w4, z0); fma2(yacc[ 9], w4, z1);
            fma2(yacc[10], w5, z0); fma2(yacc[11], w5, z1);
            fma2(yacc[12], w6, z0); fma2(yacc[13], w6, z1);
            fma2(yacc[14], w7, z0); fma2(yacc[15], w7, z1);
        }
        __syncthreads();
    }

    // ---- epilogue: BN scale/shift + bd sum + residual ----
    const float rsv = rsqrtf(1.0f + 1e-5f);
    const long obase = xbase;
    #pragma unroll
    for (int oo = 0; oo < 8; oo++) {
        int o = o0 + oo;
        float sc = gamma[o] * rsv;
        float bi = beta[o] + (bd[o] + bd[64 + o] + bd[128 + o]) * sc;
        u64 sc2 = splat2(sc), bi2 = splat2(bi);

        u64 r0 = bi2, r1 = bi2;
        fma2(r0, yacc[2*oo    ], sc2);
        fma2(r1, yacc[2*oo + 1], sc2);
        r0 = add2(r0, *(const u64*)&xs[o*RS3 + jA]);
        r1 = add2(r1, *(const u64*)&xs[o*RS3 + jB]);

        *(u64*)&out[obase + (long)o*TV_ + jA] = r0;
        *(u64*)&out[obase + (long)o*TV_ + jB] = r1;
    }
}

// ---------------------------------------------------------------------------
extern "C" void kernel_launch(void* const* d_in, const int* in_sizes, int n_in,
                              void* d_out, int out_size)
{
    const float* x     = (const float*)d_in[0];
    const float* Abase = (const float*)d_in[1];
    const float* PA    = (const float*)d_in[2];
    const float* Wa    = (const float*)d_in[3];
    const float* ba    = (const float*)d_in[4];
    const float* Wb    = (const float*)d_in[5];
    const float* bb    = (const float*)d_in[6];
    const float* Wd    = (const float*)d_in[7];
    const float* bd    = (const float*)d_in[8];
    const float* gamma = (const float*)d_in[9];
    const float* beta  = (const float*)d_in[10];
    float* out = (float*)d_out;

    cudaFuncSetAttribute(k1_att_partial, cudaFuncAttributeMaxDynamicSharedMemorySize, SMEM1_BYTES);
    cudaFuncSetAttribute(k3_out,        cudaFuncAttributeMaxDynamicSharedMemorySize, SMEM3_BYTES);

    k0_transpose<<<1, 256>>>(Wa, Wb, Wd);

    dim3 g1(NCH, N_);
    k1_att_partial<<<g1, 256, SMEM1_BYTES>>>(x, ba, bb);

    k2_softmax<<<N_*S_, 256>>>(Abase, PA);

    dim3 g3(NCH3, N_);
    k3_out<<<g3, 256, SMEM3_BYTES>>>(x, bd, gamma, beta, out);
}

// round 6
// speedup vs baseline: 1.4866x; 1.4866x over previous
#include <cuda_runtime.h>

// Problem dims
#define N_   128
#define C_   64
#define T_   288
#define V_   16
#define S_   3
#define IC_  16
#define KCT  (IC_*T_)      // 4608
#define TV_  (T_*V_)       // 4608

// Kernel 1 tiling
#define TT1  8
#define NCH  (T_/TT1)      // 36

// Kernel 3 tiling
#define TT3  8
#define J3   (TT3*V_)      // 128
#define NCH3 (T_/TT3)      // 36
#define RS3  130           // xs row stride
#define ZP   2312          // zs tf32 slice pitch (≡8 mod 32)

// Scratch (no cudaMalloc allowed)
__device__ float g_partial[(long)N_*NCH*S_*V_*V_];   // [n][ch][s][v*16+w]
__device__ float g_att[(long)N_*S_*V_*V_];           // [n][s][v*16+w]
__device__ float g_WaT[S_*C_*IC_];                   // [s][c][i]
__device__ float g_WbT[S_*C_*IC_];
__device__ uint4 g_Wfrag[S_*4*8*32];                 // tf32 B-frags [s][og][step][lane]

typedef unsigned long long u64;

__device__ __forceinline__ u64 splat2(float x) {
    u64 r; asm("mov.b64 %0, {%1, %1};" : "=l"(r) : "f"(x)); return r;
}
__device__ __forceinline__ void fma2(u64& d, u64 a, u64 b) {
    asm("fma.rn.f32x2 %0, %1, %2, %0;" : "+l"(d) : "l"(a), "l"(b));
}
__device__ __forceinline__ u64 add2(u64 a, u64 b) {
    u64 r; asm("add.rn.f32x2 %0, %1, %2;" : "=l"(r) : "l"(a), "l"(b)); return r;
}
__device__ __forceinline__ float2 unpack2(u64 a) {
    float2 r; asm("mov.b64 {%0, %1}, %2;" : "=f"(r.x), "=f"(r.y) : "l"(a)); return r;
}
__device__ __forceinline__ unsigned cvt_tf32(float f) {
    unsigned r; asm("cvt.rna.tf32.f32 %0, %1;" : "=r"(r) : "f"(f)); return r;
}
__device__ __forceinline__ void unpack2u(u64 a, unsigned& lo, unsigned& hi) {
    asm("mov.b64 {%0, %1}, %2;" : "=r"(lo), "=r"(hi) : "l"(a));
}
__device__ __forceinline__ void mma_tf32(float* d, unsigned a0, unsigned a1,
                                         unsigned a2, unsigned a3,
                                         unsigned b0, unsigned b1) {
    asm("mma.sync.aligned.m16n8k8.row.col.f32.tf32.tf32.f32 "
        "{%0,%1,%2,%3}, {%4,%5,%6,%7}, {%8,%9}, {%0,%1,%2,%3};"
        : "+f"(d[0]), "+f"(d[1]), "+f"(d[2]), "+f"(d[3])
        : "r"(a0), "r"(a1), "r"(a2), "r"(a3), "r"(b0), "r"(b1));
}

// ---------------------------------------------------------------------------
// Kernel 0: pre-transpose Wa/Wb and pre-pack Wd into tf32 mma B-fragments.
// ---------------------------------------------------------------------------
extern "C" __global__ void k0_prep(const float* __restrict__ Wa,
                                   const float* __restrict__ Wb,
                                   const float* __restrict__ Wd)
{
    const int tid = threadIdx.x;
    for (int idx = tid; idx < S_*C_*IC_; idx += 256) {
        int i = idx & 15, c = (idx >> 4) & 63, s = idx >> 10;
        g_WaT[idx] = Wa[(s*16 + i)*64 + c];
        g_WbT[idx] = Wb[(s*16 + i)*64 + c];
    }
    // B-frag pack: b0 = Wd[s][o][c], b1 = Wd[s][o][c+4] for n-tile og*16 (+8)
    for (int idx = tid; idx < S_*4*8*32; idx += 256) {
        int lane = idx & 31, step = (idx >> 5) & 7, og = (idx >> 8) & 3, s = idx >> 10;
        int o = og*16 + (lane >> 2);
        int c = step*8 + (lane & 3);
        uint4 v;
        v.x = cvt_tf32(Wd[(s*64 + o    )*64 + c    ]);
        v.y = cvt_tf32(Wd[(s*64 + o    )*64 + c + 4]);
        v.z = cvt_tf32(Wd[(s*64 + o + 8)*64 + c    ]);
        v.w = cvt_tf32(Wd[(s*64 + o + 8)*64 + c + 4]);
        g_Wfrag[idx] = v;
    }
}

// ---------------------------------------------------------------------------
// Kernel 1: att logit partials (round-2 proven config). Grid (NCH, N), 256 thr.
// ---------------------------------------------------------------------------
#define SM1_XS   0
#define SM1_FA   8192
#define SM1_FB   10240
#define SM1_WAT  12288
#define SM1_WBT  15360
#define SM1_ATTP 18432
#define SMEM1_BYTES ((18432 + 1024)*4)   // 77824 B

extern "C" __global__ void __launch_bounds__(256, 2)
k1_att_partial(const float* __restrict__ x,
               const float* __restrict__ ba, const float* __restrict__ bb)
{
    extern __shared__ float sm[];
    float* xs   = sm + SM1_XS;    // [64][128]
    float* fas  = sm + SM1_FA;    // [16][128]
    float* fbs  = sm + SM1_FB;    // [16][128]
    float* Wat  = sm + SM1_WAT;
    float* Wbt  = sm + SM1_WBT;
    float* attp = sm + SM1_ATTP;  // [4][256]

    const int ch  = blockIdx.x;
    const int n   = blockIdx.y;
    const int tid = threadIdx.x;
    const int lane = tid & 31, wrp = tid >> 5;

    const long xbase = (long)n*C_*TV_ + (long)(ch*TT1)*V_;
    for (int idx = tid; idx < 4096; idx += 256) {
        int c = idx >> 6, jp = (idx & 63)*2;
        *(u64*)&xs[c*128 + jp] = *(const u64*)&x[xbase + (long)c*TV_ + jp];
    }
    for (int idx = tid; idx < S_*C_*IC_; idx += 256) {
        Wat[idx] = g_WaT[idx];
        Wbt[idx] = g_WbT[idx];
    }
    __syncthreads();

    const int i0   = (wrp & 3)*4;
    const int jcol = 64*(wrp >> 2) + 2*lane;
    const int q  = tid >> 6;
    const int pv = (tid >> 3) & 7;
    const int pw = tid & 7;

    for (int s = 0; s < S_; s++) {
        u64 aA[4], aB[4];
        #pragma unroll
        for (int ii = 0; ii < 4; ii++) { aA[ii] = 0ull; aB[ii] = 0ull; }
        const float* wap = &Wat[s*1024];
        const float* wbp = &Wbt[s*1024];
        #pragma unroll 4
        for (int c = 0; c < 64; c++) {
            u64 xq = *(const u64*)&xs[c*128 + jcol];
            float4 wa4 = *(const float4*)&wap[c*16 + i0];
            float4 wb4 = *(const float4*)&wbp[c*16 + i0];
            fma2(aA[0], splat2(wa4.x), xq);
            fma2(aA[1], splat2(wa4.y), xq);
            fma2(aA[2], splat2(wa4.z), xq);
            fma2(aA[3], splat2(wa4.w), xq);
            fma2(aB[0], splat2(wb4.x), xq);
            fma2(aB[1], splat2(wb4.y), xq);
            fma2(aB[2], splat2(wb4.z), xq);
            fma2(aB[3], splat2(wb4.w), xq);
        }
        #pragma unroll
        for (int ii = 0; ii < 4; ii++) {
            u64 fav = add2(aA[ii], splat2(ba[s*16 + i0 + ii]));
            u64 fbv = add2(aB[ii], splat2(bb[s*16 + i0 + ii]));
            *(u64*)&fas[(i0 + ii)*128 + jcol] = fav;
            *(u64*)&fbs[(i0 + ii)*128 + jcol] = fbv;
        }
        __syncthreads();

        u64 acc0 = 0ull, acc1 = 0ull;
        #pragma unroll 8
        for (int r = 0; r < 32; r++) {
            int term = q*32 + r;
            u64 fp = *(const u64*)&fas[term*16 + 2*pv];
            u64 gp = *(const u64*)&fbs[term*16 + 2*pw];
            float2 f2 = unpack2(fp);
            fma2(acc0, splat2(f2.x), gp);
            fma2(acc1, splat2(f2.y), gp);
        }
        *(u64*)&attp[q*256 + (2*pv  )*16 + 2*pw] = acc0;
        *(u64*)&attp[q*256 + (2*pv+1)*16 + 2*pw] = acc1;
        __syncthreads();

        float red = attp[tid] + attp[256 + tid] + attp[512 + tid] + attp[768 + tid];
        g_partial[(((long)n*NCH + ch)*S_ + s)*256 + tid] = red;
    }
}

// ---------------------------------------------------------------------------
// Kernel 2: reduce chunks, /K, softmax over v, + (A_base + PA).
// ---------------------------------------------------------------------------
extern "C" __global__ void k2_softmax(const float* __restrict__ Abase,
                                      const float* __restrict__ PA)
{
    const int b = blockIdx.x;          // n*3 + s
    const int n = b / S_, s = b % S_;
    const int tid = threadIdx.x;       // v*16 + w
    const int w = tid & 15;

    __shared__ float sv[256];
    __shared__ float se[256];

    float sum = 0.f;
    const float* p = &g_partial[((long)n*NCH)*S_*256 + s*256 + tid];
    for (int chv = 0; chv < NCH; chv++) sum += p[(long)chv * (S_*256)];
    float val = sum * (1.0f / (float)KCT);

    sv[tid] = val;
    __syncthreads();
    float m = -1e30f;
    #pragma unroll
    for (int vv = 0; vv < 16; vv++) m = fmaxf(m, sv[vv*16 + w]);
    float e = expf(val - m);
    se[tid] = e;
    __syncthreads();
    float ss = 0.f;
    #pragma unroll
    for (int vv = 0; vv < 16; vv++) ss += se[vv*16 + w];

    float a = e / ss + Abase[s*256 + tid] + PA[s*256 + tid];
    g_att[(long)b*256 + tid] = a;
}

// ---------------------------------------------------------------------------
// Kernel 3: z scalar (fp32) -> tf32 zs; y via mma.sync m16n8k8 tf32;
// BN+bias+residual epilogue. Grid (NCH3, N), 256 threads.
// zs frag layout: addr(j, c) = (c&3)*ZP + j*18 + (c>>2)   [tf32 bits]
// ---------------------------------------------------------------------------
#define SM3_XS   0
#define SM3_ZS   (64*RS3)                 // 8320
#define SM3_ATT  (SM3_ZS + 4*ZP)          // 8320 + 9248 = 17568
#define SMEM3_BYTES ((SM3_ATT + S_*256)*4)   // 73344 B

extern "C" __global__ void __launch_bounds__(256, 2)
k3_out(const float* __restrict__ x,
       const float* __restrict__ bd, const float* __restrict__ gamma,
       const float* __restrict__ beta, float* __restrict__ out)
{
    extern __shared__ float sm[];
    float* xs   = sm + SM3_XS;    // [64][RS3]
    float* zs   = sm + SM3_ZS;    // frag layout / later [o][130]
    float* atts = sm + SM3_ATT;   // [s][v][w]
    unsigned* zsu = (unsigned*)zs;

    const int ch  = blockIdx.x;
    const int n   = blockIdx.y;
    const int tid = threadIdx.x;
    const int lane = tid & 31, wrp = tid >> 5;

    const long xbase = (long)n*C_*TV_ + (long)(ch*TT3)*V_;
    for (int idx = tid; idx < 64*64; idx += 256) {
        int c = idx >> 6, jp = (idx & 63)*2;
        *(u64*)&xs[c*RS3 + jp] = *(const u64*)&x[xbase + (long)c*TV_ + jp];
    }
    for (int idx = tid; idx < S_*256; idx += 256)
        atts[idx] = g_att[(long)n*S_*256 + idx];
    __syncthreads();

    // z mapping: thread owns rows {lane, lane+32} at t' = wrp
    const int ca = lane, cb = lane + 32;
    const int jz = wrp * 16;
    const int zoffA = (ca & 3)*ZP + (ca >> 2);   // + j*18
    const int zoffB = (cb & 3)*ZP + (cb >> 2);

    // y mma mapping: wrp -> (og = wrp&3 n-group, jg = wrp>>2 j-half)
    const int og = wrp & 3, jg = wrp >> 2;
    const int l4 = lane & 3, lg = lane >> 2;
    // A-frag load base: addr(j, k) = (k&3)*ZP + j*18 + (k>>2); k&3 = l4
    const int abase = l4*ZP + lg*18;             // + (j0)*18 + 2*step

    float acc[4][2][4];
    #pragma unroll
    for (int mt = 0; mt < 4; mt++)
        #pragma unroll
        for (int nt = 0; nt < 2; nt++)
            #pragma unroll
            for (int r = 0; r < 4; r++) acc[mt][nt][r] = 0.f;

    for (int s = 0; s < S_; s++) {
        // ---- z tile (scalar fp32, f32x2) ----
        u64 zacc[16];
        #pragma unroll
        for (int k = 0; k < 16; k++) zacc[k] = 0ull;
        const float* ap = &atts[s*256];
        #pragma unroll
        for (int v = 0; v < 16; v++) {
            ulonglong2 arq0 = *(const ulonglong2*)&ap[v*16 +  0];
            ulonglong2 arq1 = *(const ulonglong2*)&ap[v*16 +  4];
            ulonglong2 arq2 = *(const ulonglong2*)&ap[v*16 +  8];
            ulonglong2 arq3 = *(const ulonglong2*)&ap[v*16 + 12];
            u64 xa = splat2(xs[ca*RS3 + jz + v]);
            u64 xb = splat2(xs[cb*RS3 + jz + v]);
            fma2(zacc[0], xa, arq0.x); fma2(zacc[1], xa, arq0.y);
            fma2(zacc[2], xa, arq1.x); fma2(zacc[3], xa, arq1.y);
            fma2(zacc[4], xa, arq2.x); fma2(zacc[5], xa, arq2.y);
            fma2(zacc[6], xa, arq3.x); fma2(zacc[7], xa, arq3.y);
            fma2(zacc[ 8], xb, arq0.x); fma2(zacc[ 9], xb, arq0.y);
            fma2(zacc[10], xb, arq1.x); fma2(zacc[11], xb, arq1.y);
            fma2(zacc[12], xb, arq2.x); fma2(zacc[13], xb, arq2.y);
            fma2(zacc[14], xb, arq3.x); fma2(zacc[15], xb, arq3.y);
        }
        // store as tf32 into frag layout (conflict-free STS.32)
        #pragma unroll
        for (int p = 0; p < 8; p++) {
            float2 fa = unpack2(zacc[p]);
            float2 fb = unpack2(zacc[8 + p]);
            zsu[zoffA + (jz + 2*p    )*18] = cvt_tf32(fa.x);
            zsu[zoffA + (jz + 2*p + 1)*18] = cvt_tf32(fa.y);
            zsu[zoffB + (jz + 2*p    )*18] = cvt_tf32(fb.x);
            zsu[zoffB + (jz + 2*p + 1)*18] = cvt_tf32(fb.y);
        }
        __syncthreads();

        // ---- y mma: D[j,o] += Z[j,k] x Wd[o,k]^T over k=0..63 ----
        const uint4* wfp = &g_Wfrag[(s*4 + og)*8*32 + lane];
        #pragma unroll
        for (int step = 0; step < 8; step++) {
            uint4 bf = wfp[step*32];    // coalesced LDG.128
            #pragma unroll
            for (int mt = 0; mt < 4; mt++) {
                int ja = abase + (jg*64 + mt*16)*18 + 2*step;
                u64 lo = *(const u64*)&zsu[ja];            // a0, a2
                u64 hi = *(const u64*)&zsu[ja + 8*18];     // a1, a3
                unsigned a0, a1, a2, a3;
                unpack2u(lo, a0, a2);
                unpack2u(hi, a1, a3);
                mma_tf32(acc[mt][0], a0, a1, a2, a3, bf.x, bf.y);
                mma_tf32(acc[mt][1], a0, a1, a2, a3, bf.z, bf.w);
            }
        }
        __syncthreads();
    }

    // ---- scatter D frags to zs as [o][130] (fp32) ----
    #pragma unroll
    for (int mt = 0; mt < 4; mt++) {
        int jr = jg*64 + mt*16 + lg;
        #pragma unroll
        for (int nt = 0; nt < 2; nt++) {
            int oc = og*16 + nt*8 + 2*l4;
            zs[ oc     *130 + jr    ] = acc[mt][nt][0];
            zs[(oc + 1)*130 + jr    ] = acc[mt][nt][1];
            zs[ oc     *130 + jr + 8] = acc[mt][nt][2];
            zs[(oc + 1)*130 + jr + 8] = acc[mt][nt][3];
        }
    }
    __syncthreads();

    // ---- epilogue: BN scale/shift + bd + residual, coalesced u64 ----
    const float rsv = rsqrtf(1.0f + 1e-5f);
    const int o0 = wrp * 8;
    const int jA = 2*lane, jB = 2*lane + 64;
    #pragma unroll
    for (int oo = 0; oo < 8; oo++) {
        int o = o0 + oo;
        float sc = gamma[o] * rsv;
        float bi = beta[o] + (bd[o] + bd[64 + o] + bd[128 + o]) * sc;
        u64 sc2 = splat2(sc), bi2 = splat2(bi);

        u64 y0 = *(const u64*)&zs[o*130 + jA];
        u64 y1 = *(const u64*)&zs[o*130 + jB];
        u64 r0 = bi2, r1 = bi2;
        fma2(r0, y0, sc2);
        fma2(r1, y1, sc2);
        r0 = add2(r0, *(const u64*)&xs[o*RS3 + jA]);
        r1 = add2(r1, *(const u64*)&xs[o*RS3 + jB]);

        *(u64*)&out[xbase + (long)o*TV_ + jA] = r0;
        *(u64*)&out[xbase + (long)o*TV_ + jB] = r1;
    }
}

// ---------------------------------------------------------------------------
extern "C" void kernel_launch(void* const* d_in, const int* in_sizes, int n_in,
                              void* d_out, int out_size)
{
    const float* x     = (const float*)d_in[0];
    const float* Abase = (const float*)d_in[1];
    const float* PA    = (const float*)d_in[2];
    const float* Wa    = (const float*)d_in[3];
    const float* ba    = (const float*)d_in[4];
    const float* Wb    = (const float*)d_in[5];
    const float* bb    = (const float*)d_in[6];
    const float* Wd    = (const float*)d_in[7];
    const float* bd    = (const float*)d_in[8];
    const float* gamma = (const float*)d_in[9];
    const float* beta  = (const float*)d_in[10];
    float* out = (float*)d_out;

    cudaFuncSetAttribute(k1_att_partial, cudaFuncAttributeMaxDynamicSharedMemorySize, SMEM1_BYTES);
    cudaFuncSetAttribute(k3_out,        cudaFuncAttributeMaxDynamicSharedMemorySize, SMEM3_BYTES);

    k0_prep<<<1, 256>>>(Wa, Wb, Wd);

    dim3 g1(NCH, N_);
    k1_att_partial<<<g1, 256, SMEM1_BYTES>>>(x, ba, bb);

    k2_softmax<<<N_*S_, 256>>>(Abase, PA);

    dim3 g3(NCH3, N_);
    k3_out<<<g3, 256, SMEM3_BYTES>>>(x, bd, gamma, beta, out);
}

// round 7
// speedup vs baseline: 1.8759x; 1.2618x over previous
#include <cuda_runtime.h>

// Problem dims
#define N_   128
#define C_   64
#define T_   288
#define V_   16
#define S_   3
#define IC_  16
#define KCT  (IC_*T_)      // 4608
#define TV_  (T_*V_)       // 4608

// Kernel 1 tiling
#define TT1  8
#define NCH  (T_/TT1)      // 36
#define XS1  136           // k1 xs row stride (c-stride ≡ 8 mod 32)
#define FS1  196           // k1 fa/fb i-stride (≡ 4 mod 32)
#define FT1  24            // k1 fa/fb tp-stride

// Kernel 3 tiling
#define TT3  8
#define NCH3 (T_/TT3)      // 36
#define RS3  132           // k3 xs row stride (c-stride ≡ 4 mod 32)
#define ZP   2312          // zs tf32 slice pitch (≡ 8 mod 32)

// Scratch (no cudaMalloc allowed)
__device__ float g_partial[(long)N_*NCH*S_*V_*V_];   // [n][ch][s][v*16+w]
__device__ float g_att[(long)N_*S_*V_*V_];           // [n][s][v*16+w]
__device__ uint4 g_Wfrag[S_*4*8*32];                 // Wd tf32 B-frags [s][og][step][lane]
__device__ uint2 g_W1frag[S_*2*2*8*32];              // Wa/Wb tf32 B-frags [s][ab][nt][ks][lane]

typedef unsigned long long u64;

__device__ __forceinline__ u64 splat2(float x) {
    u64 r; asm("mov.b64 %0, {%1, %1};" : "=l"(r) : "f"(x)); return r;
}
__device__ __forceinline__ void fma2(u64& d, u64 a, u64 b) {
    asm("fma.rn.f32x2 %0, %1, %2, %0;" : "+l"(d) : "l"(a), "l"(b));
}
__device__ __forceinline__ u64 add2(u64 a, u64 b) {
    u64 r; asm("add.rn.f32x2 %0, %1, %2;" : "=l"(r) : "l"(a), "l"(b)); return r;
}
__device__ __forceinline__ unsigned cvt_tf32(float f) {
    unsigned r; asm("cvt.rna.tf32.f32 %0, %1;" : "=r"(r) : "f"(f)); return r;
}
__device__ __forceinline__ void unpack2u(u64 a, unsigned& lo, unsigned& hi) {
    asm("mov.b64 {%0, %1}, %2;" : "=r"(lo), "=r"(hi) : "l"(a));
}
__device__ __forceinline__ void mma_tf32(float* d, unsigned a0, unsigned a1,
                                         unsigned a2, unsigned a3,
                                         unsigned b0, unsigned b1) {
    asm("mma.sync.aligned.m16n8k8.row.col.f32.tf32.tf32.f32 "
        "{%0,%1,%2,%3}, {%4,%5,%6,%7}, {%8,%9}, {%0,%1,%2,%3};"
        : "+f"(d[0]), "+f"(d[1]), "+f"(d[2]), "+f"(d[3])
        : "r"(a0), "r"(a1), "r"(a2), "r"(a3), "r"(b0), "r"(b1));
}

// ---------------------------------------------------------------------------
// Kernel 0: pre-pack Wd and Wa/Wb into tf32 mma B-fragments.
// ---------------------------------------------------------------------------
extern "C" __global__ void k0_prep(const float* __restrict__ Wa,
                                   const float* __restrict__ Wb,
                                   const float* __restrict__ Wd)
{
    const int tid = threadIdx.x;
    // Wd B-frags for y-mma: b = Wd[s][o][c]
    for (int idx = tid; idx < S_*4*8*32; idx += 256) {
        int lane = idx & 31, step = (idx >> 5) & 7, og = (idx >> 8) & 3, s = idx >> 10;
        int o = og*16 + (lane >> 2);
        int c = step*8 + (lane & 3);
        uint4 v;
        v.x = cvt_tf32(Wd[(s*64 + o    )*64 + c    ]);
        v.y = cvt_tf32(Wd[(s*64 + o    )*64 + c + 4]);
        v.z = cvt_tf32(Wd[(s*64 + o + 8)*64 + c    ]);
        v.w = cvt_tf32(Wd[(s*64 + o + 8)*64 + c + 4]);
        g_Wfrag[idx] = v;
    }
    // Wa/Wb B-frags for k1 phase1: B[k=c][n=i] col-major
    for (int idx = tid; idx < S_*2*2*8*32; idx += 256) {
        int lane = idx & 31, ks = (idx >> 5) & 7, nt = (idx >> 8) & 1,
            ab = (idx >> 9) & 1, s = idx >> 10;
        int i = nt*8 + (lane >> 2);
        int c = ks*8 + (lane & 3);
        const float* W = ab ? Wb : Wa;
        uint2 v;
        v.x = cvt_tf32(W[(s*16 + i)*64 + c    ]);
        v.y = cvt_tf32(W[(s*16 + i)*64 + c + 4]);
        g_W1frag[idx] = v;
    }
}

// ---------------------------------------------------------------------------
// Kernel 1: att logit partials, fully tf32 mma. Grid (NCH, N), 256 threads.
// phase1: fa^T[j,i] = x^T[j,c] @ Wa^T[c,i]  (m=j:128, n=i:16, K=c:64)
// phase2: att[v,w]  = fa[v,k] @ fb[k,w]     (m=v:16,  n=w:16, K=(i,tp):128)
// fa/fb smem layout: addr = i*FS1 + tp*FT1 + v  (conflict-free both phases)
// ---------------------------------------------------------------------------
#define SM1_XS   0
#define SM1_FA   (64*XS1)                    // 8704
#define SM1_FB   (SM1_FA + 16*FS1)           // 11840
#define SM1_ATTP (SM1_FB + 16*FS1)           // 14976
#define SMEM1_BYTES ((SM1_ATTP + 8*256)*4)   // 68096 B

extern "C" __global__ void __launch_bounds__(256, 2)
k1_att_partial(const float* __restrict__ x,
               const float* __restrict__ ba, const float* __restrict__ bb)
{
    extern __shared__ float sm[];
    float* xs   = sm + SM1_XS;    // [64][XS1]
    float* fas  = sm + SM1_FA;    // [16 i][8 tp * FT1 + v]
    float* fbs  = sm + SM1_FB;
    float* attp = sm + SM1_ATTP;  // [8][256]
    unsigned* xsu = (unsigned*)xs;
    unsigned* fau = (unsigned*)fas;
    unsigned* fbu = (unsigned*)fbs;

    const int ch  = blockIdx.x;
    const int n   = blockIdx.y;
    const int tid = threadIdx.x;
    const int lane = tid & 31, wrp = tid >> 5;
    const int lg = lane >> 2, l4 = lane & 3;

    const long xbase = (long)n*C_*TV_ + (long)(ch*TT1)*V_;
    for (int idx = tid; idx < 4096; idx += 256) {
        int c = idx >> 6, jp = (idx & 63)*2;
        *(u64*)&xs[c*XS1 + jp] = *(const u64*)&x[xbase + (long)c*TV_ + jp];
    }
    __syncthreads();

    for (int s = 0; s < S_; s++) {
        // ---- phase 1: fa^T/fb^T via mma; warp owns j-tile [wrp*16, wrp*16+16) ----
        {
            float dA[2][4], dB[2][4];
            #pragma unroll
            for (int nt = 0; nt < 2; nt++)
                #pragma unroll
                for (int r = 0; r < 4; r++) { dA[nt][r] = 0.f; dB[nt][r] = 0.f; }

            const uint2* wfa = &g_W1frag[((s*2 + 0)*2)*8*32 + lane];
            const uint2* wfb = &g_W1frag[((s*2 + 1)*2)*8*32 + lane];
            const int j0 = wrp * 16;
            #pragma unroll
            for (int ks = 0; ks < 8; ks++) {
                // A-frags: A[j, c] = xs[c*XS1 + j]; conflict-free (8*l4 + lg)
                unsigned a0 = xsu[(ks*8 + l4    )*XS1 + j0 + lg    ];
                unsigned a1 = xsu[(ks*8 + l4    )*XS1 + j0 + lg + 8];
                unsigned a2 = xsu[(ks*8 + l4 + 4)*XS1 + j0 + lg    ];
                unsigned a3 = xsu[(ks*8 + l4 + 4)*XS1 + j0 + lg + 8];
                // fp32 bits -> tf32: cvt (rna) per element
                a0 = cvt_tf32(__uint_as_float(a0));
                a1 = cvt_tf32(__uint_as_float(a1));
                a2 = cvt_tf32(__uint_as_float(a2));
                a3 = cvt_tf32(__uint_as_float(a3));
                uint2 bA0 = wfa[(0*8 + ks)*32];
                uint2 bA1 = wfa[(1*8 + ks)*32];
                uint2 bB0 = wfb[(0*8 + ks)*32];
                uint2 bB1 = wfb[(1*8 + ks)*32];
                mma_tf32(dA[0], a0, a1, a2, a3, bA0.x, bA0.y);
                mma_tf32(dA[1], a0, a1, a2, a3, bA1.x, bA1.y);
                mma_tf32(dB[0], a0, a1, a2, a3, bB0.x, bB0.y);
                mma_tf32(dB[1], a0, a1, a2, a3, bB1.x, bB1.y);
            }
            // bias add + store to fa/fb layout (tf32 bits), tp = wrp
            #pragma unroll
            for (int nt = 0; nt < 2; nt++) {
                int i0 = nt*8 + 2*l4;
                float ba0 = __ldg(&ba[s*16 + i0]), ba1 = __ldg(&ba[s*16 + i0 + 1]);
                float bb0 = __ldg(&bb[s*16 + i0]), bb1 = __ldg(&bb[s*16 + i0 + 1]);
                int base0 =  i0     *FS1 + wrp*FT1;
                int base1 = (i0 + 1)*FS1 + wrp*FT1;
                fau[base0 + lg    ] = cvt_tf32(dA[nt][0] + ba0);
                fau[base1 + lg    ] = cvt_tf32(dA[nt][1] + ba1);
                fau[base0 + lg + 8] = cvt_tf32(dA[nt][2] + ba0);
                fau[base1 + lg + 8] = cvt_tf32(dA[nt][3] + ba1);
                fbu[base0 + lg    ] = cvt_tf32(dB[nt][0] + bb0);
                fbu[base1 + lg    ] = cvt_tf32(dB[nt][1] + bb1);
                fbu[base0 + lg + 8] = cvt_tf32(dB[nt][2] + bb0);
                fbu[base1 + lg + 8] = cvt_tf32(dB[nt][3] + bb1);
            }
        }
        __syncthreads();

        // ---- phase 2: att[v,w] partials via mma; warp owns ksteps {2w,2w+1} ----
        {
            float p[2][4];
            #pragma unroll
            for (int nt = 0; nt < 2; nt++)
                #pragma unroll
                for (int r = 0; r < 4; r++) p[nt][r] = 0.f;

            #pragma unroll
            for (int t = 0; t < 2; t++) {
                int kk = wrp*2 + t;   // kk = i index
                int ab = kk*FS1 + l4*FT1;
                unsigned a0 = fau[ab            + lg    ];
                unsigned a1 = fau[ab            + lg + 8];
                unsigned a2 = fau[kk*FS1 + (l4+4)*FT1 + lg    ];
                unsigned a3 = fau[kk*FS1 + (l4+4)*FT1 + lg + 8];
                #pragma unroll
                for (int nt = 0; nt < 2; nt++) {
                    unsigned b0 = fbu[ab            + nt*8 + lg];
                    unsigned b1 = fbu[kk*FS1 + (l4+4)*FT1 + nt*8 + lg];
                    mma_tf32(p[nt], a0, a1, a2, a3, b0, b1);
                }
            }
            // store partials to attp[wrp][v*16+w]
            float* ap = &attp[wrp*256];
            #pragma unroll
            for (int nt = 0; nt < 2; nt++) {
                int w0 = nt*8 + 2*l4;
                ap[ lg     *16 + w0    ] = p[nt][0];
                ap[ lg     *16 + w0 + 1] = p[nt][1];
                ap[(lg + 8)*16 + w0    ] = p[nt][2];
                ap[(lg + 8)*16 + w0 + 1] = p[nt][3];
            }
        }
        __syncthreads();

        float red = 0.f;
        #pragma unroll
        for (int w = 0; w < 8; w++) red += attp[w*256 + tid];
        g_partial[(((long)n*NCH + ch)*S_ + s)*256 + tid] = red;
        // next-iter sync (after phase1) protects attp/fas reuse
    }
}

// ---------------------------------------------------------------------------
// Kernel 2: reduce chunks, /K, softmax over v, + (A_base + PA).
// ---------------------------------------------------------------------------
extern "C" __global__ void k2_softmax(const float* __restrict__ Abase,
                                      const float* __restrict__ PA)
{
    const int b = blockIdx.x;          // n*3 + s
    const int n = b / S_, s = b % S_;
    const int tid = threadIdx.x;       // v*16 + w
    const int w = tid & 15;

    __shared__ float sv[256];
    __shared__ float se[256];

    float sum = 0.f;
    const float* p = &g_partial[((long)n*NCH)*S_*256 + s*256 + tid];
    for (int chv = 0; chv < NCH; chv++) sum += p[(long)chv * (S_*256)];
    float val = sum * (1.0f / (float)KCT);

    sv[tid] = val;
    __syncthreads();
    float m = -1e30f;
    #pragma unroll
    for (int vv = 0; vv < 16; vv++) m = fmaxf(m, sv[vv*16 + w]);
    float e = expf(val - m);
    se[tid] = e;
    __syncthreads();
    float ss = 0.f;
    #pragma unroll
    for (int vv = 0; vv < 16; vv++) ss += se[vv*16 + w];

    float a = e / ss + Abase[s*256 + tid] + PA[s*256 + tid];
    g_att[(long)b*256 + tid] = a;
}

// ---------------------------------------------------------------------------
// Kernel 3: z via mma (A = xs, B = att frags), cvt->tf32 frag store,
// y via mma (A = z frags, B = Wd frags), BN+bias+residual epilogue.
// Grid (NCH3, N), 256 threads.
// ---------------------------------------------------------------------------
#define SM3_XS   0
#define SM3_ZS   (64*RS3)                 // 8448
#define SM3_ATT  (SM3_ZS + 4*ZP)          // 17696
#define SMEM3_BYTES ((SM3_ATT + S_*256)*4)   // 73856 B

extern "C" __global__ void __launch_bounds__(256, 2)
k3_out(const float* __restrict__ x,
       const float* __restrict__ bd, const float* __restrict__ gamma,
       const float* __restrict__ beta, float* __restrict__ out)
{
    extern __shared__ float sm[];
    float* xs   = sm + SM3_XS;    // [64][RS3]
    float* zs   = sm + SM3_ZS;    // z tf32 frags / later y [o][130]
    float* atts = sm + SM3_ATT;   // [s][v][w]
    unsigned* zsu = (unsigned*)zs;
    unsigned* xsu = (unsigned*)xs;

    const int ch  = blockIdx.x;
    const int n   = blockIdx.y;
    const int tid = threadIdx.x;
    const int lane = tid & 31, wrp = tid >> 5;
    const int lg = lane >> 2, l4 = lane & 3;

    const long xbase = (long)n*C_*TV_ + (long)(ch*TT3)*V_;
    for (int idx = tid; idx < 4096; idx += 256) {
        int c = idx >> 6, jp = (idx & 63)*2;
        *(u64*)&xs[c*RS3 + jp] = *(const u64*)&x[xbase + (long)c*TV_ + jp];
    }
    for (int idx = tid; idx < S_*256; idx += 256)
        atts[idx] = g_att[(long)n*S_*256 + idx];
    __syncthreads();

    // y mma mapping: wrp -> (og = wrp&3 n-group, jg = wrp>>2 j-half)
    const int og = wrp & 3, jg = wrp >> 2;
    const int abase = l4*ZP + lg*18;

    float acc[4][2][4];
    #pragma unroll
    for (int mt = 0; mt < 4; mt++)
        #pragma unroll
        for (int nt = 0; nt < 2; nt++)
            #pragma unroll
            for (int r = 0; r < 4; r++) acc[mt][nt][r] = 0.f;

    for (int s = 0; s < S_; s++) {
        // ---- z tile via mma: z[c,w] = sum_v xs[c, t'v] att[v,w]; t' = wrp ----
        {
            // B-frags from att (tf32 cvt, tiny)
            unsigned bf[2][2][2];  // [ks][nt][b0/b1]
            const float* ap = &atts[s*256];
            #pragma unroll
            for (int ks = 0; ks < 2; ks++)
                #pragma unroll
                for (int nt = 0; nt < 2; nt++) {
                    bf[ks][nt][0] = cvt_tf32(ap[(ks*8 + l4    )*16 + nt*8 + lg]);
                    bf[ks][nt][1] = cvt_tf32(ap[(ks*8 + l4 + 4)*16 + nt*8 + lg]);
                }
            #pragma unroll
            for (int mt = 0; mt < 4; mt++) {
                float d[2][4];
                #pragma unroll
                for (int nt = 0; nt < 2; nt++)
                    #pragma unroll
                    for (int r = 0; r < 4; r++) d[nt][r] = 0.f;
                #pragma unroll
                for (int ks = 0; ks < 2; ks++) {
                    // A-frags: xs[(mt*16+row)*RS3 + wrp*16 + col]; conflict-free
                    int ra = (mt*16 + lg)*RS3 + wrp*16 + ks*8 + l4;
                    unsigned a0 = cvt_tf32(__uint_as_float(xsu[ra          ]));
                    unsigned a1 = cvt_tf32(__uint_as_float(xsu[ra + 8*RS3  ]));
                    unsigned a2 = cvt_tf32(__uint_as_float(xsu[ra + 4      ]));
                    unsigned a3 = cvt_tf32(__uint_as_float(xsu[ra + 8*RS3+4]));
                    mma_tf32(d[0], a0, a1, a2, a3, bf[ks][0][0], bf[ks][0][1]);
                    mma_tf32(d[1], a0, a1, a2, a3, bf[ks][1][0], bf[ks][1][1]);
                }
                // cvt -> tf32, scatter into y A-frag layout
                #pragma unroll
                for (int nt = 0; nt < 2; nt++) {
                    int c0 = mt*16 + lg;
                    int j0 = wrp*16 + nt*8 + 2*l4;
                    zsu[((c0    )&3)*ZP + (j0    )*18 + ((c0    )>>2)] = cvt_tf32(d[nt][0]);
                    zsu[((c0    )&3)*ZP + (j0 + 1)*18 + ((c0    )>>2)] = cvt_tf32(d[nt][1]);
                    zsu[((c0 + 8)&3)*ZP + (j0    )*18 + ((c0 + 8)>>2)] = cvt_tf32(d[nt][2]);
                    zsu[((c0 + 8)&3)*ZP + (j0 + 1)*18 + ((c0 + 8)>>2)] = cvt_tf32(d[nt][3]);
                }
            }
        }
        __syncthreads();

        // ---- y mma: D[j,o] += Z[j,k] x Wd[o,k]^T over k=0..63 ----
        const uint4* wfp = &g_Wfrag[(s*4 + og)*8*32 + lane];
        #pragma unroll
        for (int step = 0; step < 8; step++) {
            uint4 bfw = wfp[step*32];    // coalesced LDG.128
            #pragma unroll
            for (int mt = 0; mt < 4; mt++) {
                int ja = abase + (jg*64 + mt*16)*18 + 2*step;
                u64 lo = *(const u64*)&zsu[ja];            // a0, a2
                u64 hi = *(const u64*)&zsu[ja + 8*18];     // a1, a3
                unsigned a0, a1, a2, a3;
                unpack2u(lo, a0, a2);
                unpack2u(hi, a1, a3);
                mma_tf32(acc[mt][0], a0, a1, a2, a3, bfw.x, bfw.y);
                mma_tf32(acc[mt][1], a0, a1, a2, a3, bfw.z, bfw.w);
            }
        }
        __syncthreads();
    }

    // ---- scatter y D-frags to zs as [o][130] (fp32) ----
    #pragma unroll
    for (int mt = 0; mt < 4; mt++) {
        int jr = jg*64 + mt*16 + lg;
        #pragma unroll
        for (int nt = 0; nt < 2; nt++) {
            int oc = og*16 + nt*8 + 2*l4;
            zs[ oc     *130 + jr    ] = acc[mt][nt][0];
            zs[(oc + 1)*130 + jr    ] = acc[mt][nt][1];
            zs[ oc     *130 + jr + 8] = acc[mt][nt][2];
            zs[(oc + 1)*130 + jr + 8] = acc[mt][nt][3];
        }
    }
    __syncthreads();

    // ---- epilogue: BN scale/shift + bd + residual, coalesced u64 ----
    const float rsv = rsqrtf(1.0f + 1e-5f);
    const int o0 = wrp * 8;
    const int jA = 2*lane, jB = 2*lane + 64;
    #pragma unroll
    for (int oo = 0; oo < 8; oo++) {
        int o = o0 + oo;
        float sc = gamma[o] * rsv;
        float bi = beta[o] + (bd[o] + bd[64 + o] + bd[128 + o]) * sc;
        u64 sc2 = splat2(sc), bi2 = splat2(bi);

        u64 y0 = *(const u64*)&zs[o*130 + jA];
        u64 y1 = *(const u64*)&zs[o*130 + jB];
        u64 r0 = bi2, r1 = bi2;
        fma2(r0, y0, sc2);
        fma2(r1, y1, sc2);
        r0 = add2(r0, *(const u64*)&xs[o*RS3 + jA]);
        r1 = add2(r1, *(const u64*)&xs[o*RS3 + jB]);

        *(u64*)&out[xbase + (long)o*TV_ + jA] = r0;
        *(u64*)&out[xbase + (long)o*TV_ + jB] = r1;
    }
}

// ---------------------------------------------------------------------------
extern "C" void kernel_launch(void* const* d_in, const int* in_sizes, int n_in,
                              void* d_out, int out_size)
{
    const float* x     = (const float*)d_in[0];
    const float* Abase = (const float*)d_in[1];
    const float* PA    = (const float*)d_in[2];
    const float* Wa    = (const float*)d_in[3];
    const float* ba    = (const float*)d_in[4];
    const float* Wb    = (const float*)d_in[5];
    const float* bb    = (const float*)d_in[6];
    const float* Wd    = (const float*)d_in[7];
    const float* bd    = (const float*)d_in[8];
    const float* gamma = (const float*)d_in[9];
    const float* beta  = (const float*)d_in[10];
    float* out = (float*)d_out;

    cudaFuncSetAttribute(k1_att_partial, cudaFuncAttributeMaxDynamicSharedMemorySize, SMEM1_BYTES);
    cudaFuncSetAttribute(k3_out,        cudaFuncAttributeMaxDynamicSharedMemorySize, SMEM3_BYTES);

    k0_prep<<<1, 256>>>(Wa, Wb, Wd);

    dim3 g1(NCH, N_);
    k1_att_partial<<<g1, 256, SMEM1_BYTES>>>(x, ba, bb);

    k2_softmax<<<N_*S_, 256>>>(Abase, PA);

    dim3 g3(NCH3, N_);
    k3_out<<<g3, 256, SMEM3_BYTES>>>(x, bd, gamma, beta, out);
}

// round 8
// speedup vs baseline: 2.3845x; 1.2712x over previous
#include <cuda_runtime.h>

// Problem dims
#define N_   128
#define C_   64
#define T_   288
#define V_   16
#define S_   3
#define IC_  16
#define KCT  (IC_*T_)      // 4608
#define TV_  (T_*V_)       // 4608

// Kernel 1 tiling
#define TT1  8
#define NCH  (T_/TT1)      // 36
#define XS1  136           // k1 xs row stride (c-stride ≡ 8 mod 32)
#define FS1  196           // k1 fa/fb i-stride (≡ 4 mod 32)
#define FT1  24            // k1 fa/fb tp-stride

// Kernel 3 tiling
#define TT3  8
#define NCH3 (T_/TT3)      // 36
#define RS3  132           // k3 xs row stride (c-stride ≡ 4 mod 32)
#define ZP   2312          // zs tf32 slice pitch (≡ 8 mod 32)

// Scratch (no cudaMalloc allowed)
__device__ float g_partial[(long)N_*NCH*S_*V_*V_];   // [n][ch][s][v*16+w]
__device__ float g_att[(long)N_*S_*V_*V_];           // [n][s][v*16+w]
__device__ uint4 g_Wfrag[S_*4*8*32];                 // Wd tf32 B-frags [s][og][step][lane]
__device__ uint2 g_W1frag[S_*2*2*8*32];              // Wa/Wb tf32 B-frags [s][ab][nt][ks][lane]

typedef unsigned long long u64;

__device__ __forceinline__ u64 splat2(float x) {
    u64 r; asm("mov.b64 %0, {%1, %1};" : "=l"(r) : "f"(x)); return r;
}
__device__ __forceinline__ void fma2(u64& d, u64 a, u64 b) {
    asm("fma.rn.f32x2 %0, %1, %2, %0;" : "+l"(d) : "l"(a), "l"(b));
}
__device__ __forceinline__ u64 add2(u64 a, u64 b) {
    u64 r; asm("add.rn.f32x2 %0, %1, %2;" : "=l"(r) : "l"(a), "l"(b)); return r;
}
__device__ __forceinline__ unsigned cvt_tf32(float f) {
    unsigned r; asm("cvt.rna.tf32.f32 %0, %1;" : "=r"(r) : "f"(f)); return r;
}
__device__ __forceinline__ void unpack2u(u64 a, unsigned& lo, unsigned& hi) {
    asm("mov.b64 {%0, %1}, %2;" : "=r"(lo), "=r"(hi) : "l"(a));
}
__device__ __forceinline__ void mma_tf32(float* d, unsigned a0, unsigned a1,
                                         unsigned a2, unsigned a3,
                                         unsigned b0, unsigned b1) {
    asm("mma.sync.aligned.m16n8k8.row.col.f32.tf32.tf32.f32 "
        "{%0,%1,%2,%3}, {%4,%5,%6,%7}, {%8,%9}, {%0,%1,%2,%3};"
        : "+f"(d[0]), "+f"(d[1]), "+f"(d[2]), "+f"(d[3])
        : "r"(a0), "r"(a1), "r"(a2), "r"(a3), "r"(b0), "r"(b1));
}
// per-half named barrier (128 threads each; id must be warp-uniform in half)
__device__ __forceinline__ void bar_half(int id) {
    asm volatile("bar.sync %0, 128;" :: "r"(id) : "memory");
}

// ---------------------------------------------------------------------------
// Kernel 0: pre-pack Wd and Wa/Wb into tf32 mma B-fragments.
// ---------------------------------------------------------------------------
extern "C" __global__ void k0_prep(const float* __restrict__ Wa,
                                   const float* __restrict__ Wb,
                                   const float* __restrict__ Wd)
{
    const int tid = threadIdx.x;
    for (int idx = tid; idx < S_*4*8*32; idx += 256) {
        int lane = idx & 31, step = (idx >> 5) & 7, og = (idx >> 8) & 3, s = idx >> 10;
        int o = og*16 + (lane >> 2);
        int c = step*8 + (lane & 3);
        uint4 v;
        v.x = cvt_tf32(Wd[(s*64 + o    )*64 + c    ]);
        v.y = cvt_tf32(Wd[(s*64 + o    )*64 + c + 4]);
        v.z = cvt_tf32(Wd[(s*64 + o + 8)*64 + c    ]);
        v.w = cvt_tf32(Wd[(s*64 + o + 8)*64 + c + 4]);
        g_Wfrag[idx] = v;
    }
    for (int idx = tid; idx < S_*2*2*8*32; idx += 256) {
        int lane = idx & 31, ks = (idx >> 5) & 7, nt = (idx >> 8) & 1,
            ab = (idx >> 9) & 1, s = idx >> 10;
        int i = nt*8 + (lane >> 2);
        int c = ks*8 + (lane & 3);
        const float* W = ab ? Wb : Wa;
        uint2 v;
        v.x = cvt_tf32(W[(s*16 + i)*64 + c    ]);
        v.y = cvt_tf32(W[(s*16 + i)*64 + c + 4]);
        g_W1frag[idx] = v;
    }
}

// ---------------------------------------------------------------------------
// Kernel 1: att logit partials, fully tf32 mma. Grid (NCH, N), 256 threads.
// ---------------------------------------------------------------------------
#define SM1_XS   0
#define SM1_FA   (64*XS1)                    // 8704
#define SM1_FB   (SM1_FA + 16*FS1)           // 11840
#define SM1_ATTP (SM1_FB + 16*FS1)           // 14976
#define SMEM1_BYTES ((SM1_ATTP + 8*256)*4)   // 68096 B

extern "C" __global__ void __launch_bounds__(256, 3)
k1_att_partial(const float* __restrict__ x,
               const float* __restrict__ ba, const float* __restrict__ bb)
{
    extern __shared__ float sm[];
    float* xs   = sm + SM1_XS;    // [64][XS1]
    float* fas  = sm + SM1_FA;    // [16 i][8 tp * FT1 + v]
    float* fbs  = sm + SM1_FB;
    float* attp = sm + SM1_ATTP;  // [8][256]
    unsigned* xsu = (unsigned*)xs;
    unsigned* fau = (unsigned*)fas;
    unsigned* fbu = (unsigned*)fbs;

    const int ch  = blockIdx.x;
    const int n   = blockIdx.y;
    const int tid = threadIdx.x;
    const int lane = tid & 31, wrp = tid >> 5;
    const int lg = lane >> 2, l4 = lane & 3;

    const long xbase = (long)n*C_*TV_ + (long)(ch*TT1)*V_;
    for (int idx = tid; idx < 4096; idx += 256) {
        int c = idx >> 6, jp = (idx & 63)*2;
        *(u64*)&xs[c*XS1 + jp] = *(const u64*)&x[xbase + (long)c*TV_ + jp];
    }
    __syncthreads();

    for (int s = 0; s < S_; s++) {
        // ---- phase 1: fa^T/fb^T via mma; warp owns j-tile [wrp*16, +16) ----
        {
            float dA[2][4], dB[2][4];
            #pragma unroll
            for (int nt = 0; nt < 2; nt++)
                #pragma unroll
                for (int r = 0; r < 4; r++) { dA[nt][r] = 0.f; dB[nt][r] = 0.f; }

            const uint2* wfa = &g_W1frag[((s*2 + 0)*2)*8*32 + lane];
            const uint2* wfb = &g_W1frag[((s*2 + 1)*2)*8*32 + lane];
            const int j0 = wrp * 16;
            #pragma unroll
            for (int ks = 0; ks < 8; ks++) {
                unsigned a0 = xsu[(ks*8 + l4    )*XS1 + j0 + lg    ];
                unsigned a1 = xsu[(ks*8 + l4    )*XS1 + j0 + lg + 8];
                unsigned a2 = xsu[(ks*8 + l4 + 4)*XS1 + j0 + lg    ];
                unsigned a3 = xsu[(ks*8 + l4 + 4)*XS1 + j0 + lg + 8];
                a0 = cvt_tf32(__uint_as_float(a0));
                a1 = cvt_tf32(__uint_as_float(a1));
                a2 = cvt_tf32(__uint_as_float(a2));
                a3 = cvt_tf32(__uint_as_float(a3));
                uint2 bA0 = wfa[(0*8 + ks)*32];
                uint2 bA1 = wfa[(1*8 + ks)*32];
                uint2 bB0 = wfb[(0*8 + ks)*32];
                uint2 bB1 = wfb[(1*8 + ks)*32];
                mma_tf32(dA[0], a0, a1, a2, a3, bA0.x, bA0.y);
                mma_tf32(dA[1], a0, a1, a2, a3, bA1.x, bA1.y);
                mma_tf32(dB[0], a0, a1, a2, a3, bB0.x, bB0.y);
                mma_tf32(dB[1], a0, a1, a2, a3, bB1.x, bB1.y);
            }
            #pragma unroll
            for (int nt = 0; nt < 2; nt++) {
                int i0 = nt*8 + 2*l4;
                float ba0 = __ldg(&ba[s*16 + i0]), ba1 = __ldg(&ba[s*16 + i0 + 1]);
                float bb0 = __ldg(&bb[s*16 + i0]), bb1 = __ldg(&bb[s*16 + i0 + 1]);
                int base0 =  i0     *FS1 + wrp*FT1;
                int base1 = (i0 + 1)*FS1 + wrp*FT1;
                fau[base0 + lg    ] = cvt_tf32(dA[nt][0] + ba0);
                fau[base1 + lg    ] = cvt_tf32(dA[nt][1] + ba1);
                fau[base0 + lg + 8] = cvt_tf32(dA[nt][2] + ba0);
                fau[base1 + lg + 8] = cvt_tf32(dA[nt][3] + ba1);
                fbu[base0 + lg    ] = cvt_tf32(dB[nt][0] + bb0);
                fbu[base1 + lg    ] = cvt_tf32(dB[nt][1] + bb1);
                fbu[base0 + lg + 8] = cvt_tf32(dB[nt][2] + bb0);
                fbu[base1 + lg + 8] = cvt_tf32(dB[nt][3] + bb1);
            }
        }
        __syncthreads();

        // ---- phase 2: att[v,w] partials via mma; warp owns i in {2w, 2w+1} ----
        {
            float p[2][4];
            #pragma unroll
            for (int nt = 0; nt < 2; nt++)
                #pragma unroll
                for (int r = 0; r < 4; r++) p[nt][r] = 0.f;

            #pragma unroll
            for (int t = 0; t < 2; t++) {
                int kk = wrp*2 + t;
                int ab = kk*FS1 + l4*FT1;
                unsigned a0 = fau[ab                  + lg    ];
                unsigned a1 = fau[ab                  + lg + 8];
                unsigned a2 = fau[kk*FS1 + (l4+4)*FT1 + lg    ];
                unsigned a3 = fau[kk*FS1 + (l4+4)*FT1 + lg + 8];
                #pragma unroll
                for (int nt = 0; nt < 2; nt++) {
                    unsigned b0 = fbu[ab                  + nt*8 + lg];
                    unsigned b1 = fbu[kk*FS1 + (l4+4)*FT1 + nt*8 + lg];
                    mma_tf32(p[nt], a0, a1, a2, a3, b0, b1);
                }
            }
            float* ap = &attp[wrp*256];
            #pragma unroll
            for (int nt = 0; nt < 2; nt++) {
                int w0 = nt*8 + 2*l4;
                ap[ lg     *16 + w0    ] = p[nt][0];
                ap[ lg     *16 + w0 + 1] = p[nt][1];
                ap[(lg + 8)*16 + w0    ] = p[nt][2];
                ap[(lg + 8)*16 + w0 + 1] = p[nt][3];
            }
        }
        __syncthreads();

        float red = 0.f;
        #pragma unroll
        for (int w = 0; w < 8; w++) red += attp[w*256 + tid];
        g_partial[(((long)n*NCH + ch)*S_ + s)*256 + tid] = red;
    }
}

// ---------------------------------------------------------------------------
// Kernel 2: reduce chunks, /K, softmax over v, + (A_base + PA).
// ---------------------------------------------------------------------------
extern "C" __global__ void k2_softmax(const float* __restrict__ Abase,
                                      const float* __restrict__ PA)
{
    const int b = blockIdx.x;          // n*3 + s
    const int n = b / S_, s = b % S_;
    const int tid = threadIdx.x;       // v*16 + w
    const int w = tid & 15;

    __shared__ float sv[256];
    __shared__ float se[256];

    float sum = 0.f;
    const float* p = &g_partial[((long)n*NCH)*S_*256 + s*256 + tid];
    for (int chv = 0; chv < NCH; chv++) sum += p[(long)chv * (S_*256)];
    float val = sum * (1.0f / (float)KCT);

    sv[tid] = val;
    __syncthreads();
    float m = -1e30f;
    #pragma unroll
    for (int vv = 0; vv < 16; vv++) m = fmaxf(m, sv[vv*16 + w]);
    float e = expf(val - m);
    se[tid] = e;
    __syncthreads();
    float ss = 0.f;
    #pragma unroll
    for (int vv = 0; vv < 16; vv++) ss += se[vv*16 + w];

    float a = e / ss + Abase[s*256 + tid] + PA[s*256 + tid];
    g_att[(long)b*256 + tid] = a;
}

// ---------------------------------------------------------------------------
// Kernel 3: z via mma, y via mma, BN+bias+residual. Grid (NCH3, N), 256 thr.
// In-loop syncs are PER-HALF named barriers: warps 0-3 produce/consume only
// j in [0,64), warps 4-7 only [64,128) — closed groups.
// ---------------------------------------------------------------------------
#define SM3_XS   0
#define SM3_ZS   (64*RS3)                 // 8448
#define SM3_ATT  (SM3_ZS + 4*ZP)          // 17696
#define SMEM3_BYTES ((SM3_ATT + S_*256)*4)   // 73856 B

extern "C" __global__ void __launch_bounds__(256, 3)
k3_out(const float* __restrict__ x,
       const float* __restrict__ bd, const float* __restrict__ gamma,
       const float* __restrict__ beta, float* __restrict__ out)
{
    extern __shared__ float sm[];
    float* xs   = sm + SM3_XS;    // [64][RS3]
    float* zs   = sm + SM3_ZS;    // z tf32 frags / later y [o][130]
    float* atts = sm + SM3_ATT;   // [s][v][w]
    unsigned* zsu = (unsigned*)zs;
    unsigned* xsu = (unsigned*)xs;

    const int ch  = blockIdx.x;
    const int n   = blockIdx.y;
    const int tid = threadIdx.x;
    const int lane = tid & 31, wrp = tid >> 5;
    const int lg = lane >> 2, l4 = lane & 3;
    const int half_id = 1 + (wrp >> 2);    // 1 for warps 0-3, 2 for 4-7

    const long xbase = (long)n*C_*TV_ + (long)(ch*TT3)*V_;
    for (int idx = tid; idx < 4096; idx += 256) {
        int c = idx >> 6, jp = (idx & 63)*2;
        *(u64*)&xs[c*RS3 + jp] = *(const u64*)&x[xbase + (long)c*TV_ + jp];
    }
    for (int idx = tid; idx < S_*256; idx += 256)
        atts[idx] = g_att[(long)n*S_*256 + idx];
    __syncthreads();

    const int og = wrp & 3, jg = wrp >> 2;
    const int abase = l4*ZP + lg*18;

    float acc[4][2][4];
    #pragma unroll
    for (int mt = 0; mt < 4; mt++)
        #pragma unroll
        for (int nt = 0; nt < 2; nt++)
            #pragma unroll
            for (int r = 0; r < 4; r++) acc[mt][nt][r] = 0.f;

    for (int s = 0; s < S_; s++) {
        // ---- z tile via mma: z[c,w] for t' = wrp ----
        {
            unsigned bf[2][2][2];  // [ks][nt][b0/b1]
            const float* ap = &atts[s*256];
            #pragma unroll
            for (int ks = 0; ks < 2; ks++)
                #pragma unroll
                for (int nt = 0; nt < 2; nt++) {
                    bf[ks][nt][0] = cvt_tf32(ap[(ks*8 + l4    )*16 + nt*8 + lg]);
                    bf[ks][nt][1] = cvt_tf32(ap[(ks*8 + l4 + 4)*16 + nt*8 + lg]);
                }
            #pragma unroll
            for (int mt = 0; mt < 4; mt++) {
                float d[2][4];
                #pragma unroll
                for (int nt = 0; nt < 2; nt++)
                    #pragma unroll
                    for (int r = 0; r < 4; r++) d[nt][r] = 0.f;
                #pragma unroll
                for (int ks = 0; ks < 2; ks++) {
                    int ra = (mt*16 + lg)*RS3 + wrp*16 + ks*8 + l4;
                    unsigned a0 = cvt_tf32(__uint_as_float(xsu[ra          ]));
                    unsigned a1 = cvt_tf32(__uint_as_float(xsu[ra + 8*RS3  ]));
                    unsigned a2 = cvt_tf32(__uint_as_float(xsu[ra + 4      ]));
                    unsigned a3 = cvt_tf32(__uint_as_float(xsu[ra + 8*RS3+4]));
                    mma_tf32(d[0], a0, a1, a2, a3, bf[ks][0][0], bf[ks][0][1]);
                    mma_tf32(d[1], a0, a1, a2, a3, bf[ks][1][0], bf[ks][1][1]);
                }
                #pragma unroll
                for (int nt = 0; nt < 2; nt++) {
                    int c0 = mt*16 + lg;
                    int j0 = wrp*16 + nt*8 + 2*l4;
                    zsu[((c0    )&3)*ZP + (j0    )*18 + ((c0    )>>2)] = cvt_tf32(d[nt][0]);
                    zsu[((c0    )&3)*ZP + (j0 + 1)*18 + ((c0    )>>2)] = cvt_tf32(d[nt][1]);
                    zsu[((c0 + 8)&3)*ZP + (j0    )*18 + ((c0 + 8)>>2)] = cvt_tf32(d[nt][2]);
                    zsu[((c0 + 8)&3)*ZP + (j0 + 1)*18 + ((c0 + 8)>>2)] = cvt_tf32(d[nt][3]);
                }
            }
        }
        bar_half(half_id);   // z(j-half) ready for this half's consumers

        // ---- y mma: D[j,o] += Z[j,k] x Wd[o,k]^T over k=0..63 ----
        const uint4* wfp = &g_Wfrag[(s*4 + og)*8*32 + lane];
        #pragma unroll
        for (int step = 0; step < 8; step++) {
            uint4 bfw = wfp[step*32];    // coalesced LDG.128
            #pragma unroll
            for (int mt = 0; mt < 4; mt++) {
                int ja = abase + (jg*64 + mt*16)*18 + 2*step;
                u64 lo = *(const u64*)&zsu[ja];            // a0, a2
                u64 hi = *(const u64*)&zsu[ja + 8*18];     // a1, a3
                unsigned a0, a1, a2, a3;
                unpack2u(lo, a0, a2);
                unpack2u(hi, a1, a3);
                mma_tf32(acc[mt][0], a0, a1, a2, a3, bfw.x, bfw.y);
                mma_tf32(acc[mt][1], a0, a1, a2, a3, bfw.z, bfw.w);
            }
        }
        bar_half(half_id);   // this half may overwrite its z frags next s
    }
    __syncthreads();         // cross-half: scatter aliases zs frag region

    // ---- scatter y D-frags to zs as [o][130] (fp32) ----
    #pragma unroll
    for (int mt = 0; mt < 4; mt++) {
        int jr = jg*64 + mt*16 + lg;
        #pragma unroll
        for (int nt = 0; nt < 2; nt++) {
            int oc = og*16 + nt*8 + 2*l4;
            zs[ oc     *130 + jr    ] = acc[mt][nt][0];
            zs[(oc + 1)*130 + jr    ] = acc[mt][nt][1];
            zs[ oc     *130 + jr + 8] = acc[mt][nt][2];
            zs[(oc + 1)*130 + jr + 8] = acc[mt][nt][3];
        }
    }
    __syncthreads();

    // ---- epilogue: BN scale/shift + bd + residual, coalesced u64 ----
    const float rsv = rsqrtf(1.0f + 1e-5f);
    const int o0 = wrp * 8;
    const int jA = 2*lane, jB = 2*lane + 64;
    #pragma unroll
    for (int oo = 0; oo < 8; oo++) {
        int o = o0 + oo;
        float sc = gamma[o] * rsv;
        float bi = beta[o] + (bd[o] + bd[64 + o] + bd[128 + o]) * sc;
        u64 sc2 = splat2(sc), bi2 = splat2(bi);

        u64 y0 = *(const u64*)&zs[o*130 + jA];
        u64 y1 = *(const u64*)&zs[o*130 + jB];
        u64 r0 = bi2, r1 = bi2;
        fma2(r0, y0, sc2);
        fma2(r1, y1, sc2);
        r0 = add2(r0, *(const u64*)&xs[o*RS3 + jA]);
        r1 = add2(r1, *(const u64*)&xs[o*RS3 + jB]);

        *(u64*)&out[xbase + (long)o*TV_ + jA] = r0;
        *(u64*)&out[xbase + (long)o*TV_ + jB] = r1;
    }
}

// ---------------------------------------------------------------------------
extern "C" void kernel_launch(void* const* d_in, const int* in_sizes, int n_in,
                              void* d_out, int out_size)
{
    const float* x     = (const float*)d_in[0];
    const float* Abase = (const float*)d_in[1];
    const float* PA    = (const float*)d_in[2];
    const float* Wa    = (const float*)d_in[3];
    const float* ba    = (const float*)d_in[4];
    const float* Wb    = (const float*)d_in[5];
    const float* bb    = (const float*)d_in[6];
    const float* Wd    = (const float*)d_in[7];
    const float* bd    = (const float*)d_in[8];
    const float* gamma = (const float*)d_in[9];
    const float* beta  = (const float*)d_in[10];
    float* out = (float*)d_out;

    cudaFuncSetAttribute(k1_att_partial, cudaFuncAttributeMaxDynamicSharedMemorySize, SMEM1_BYTES);
    cudaFuncSetAttribute(k3_out,        cudaFuncAttributeMaxDynamicSharedMemorySize, SMEM3_BYTES);

    k0_prep<<<1, 256>>>(Wa, Wb, Wd);

    dim3 g1(NCH, N_);
    k1_att_partial<<<g1, 256, SMEM1_BYTES>>>(x, ba, bb);

    k2_softmax<<<N_*S_, 256>>>(Abase, PA);

    dim3 g3(NCH3, N_);
    k3_out<<<g3, 256, SMEM3_BYTES>>>(x, bd, gamma, beta, out);
}